// round 2
// baseline (speedup 1.0000x reference)
#include <cuda_runtime.h>
#include <cstdint>

// Problem constants
#define Bq   1024
#define Nn   128
#define Dd   256
#define Hh   8
#define DHd  32
#define NEGV (-1e9f)
#define CLIPV 10.0f
#define INV_SQRT_DH 0.17677669529663687f  // 1/sqrt(32)
#define INV_SQRT_D  0.0625f               // 1/sqrt(256)

// streaming load: cache in L2, bypass L1 (protects Woc residency in L1)
__device__ __forceinline__ float ldcg(const float* p) { return __ldcg(p); }

// ---------------- scratch (device globals; no cudaMalloc allowed) ----------
__device__ float g_KT  [Bq * Dd * Nn];   // [b][d][n]  (E@Wk, transposed)
__device__ float g_V   [Bq * Nn * Dd];   // [b][n][d]  (E@Wv)
__device__ float g_LK2T[Bq * Dd * Nn];   // [b][d][n]  (E@(Wlk@Wo^T), transposed)
__device__ float g_P   [Bq * Nn * Dd];   // [b][n][d]  (E@Ws_bot)
__device__ float g_q0  [Bq * Dd];        // step-0 query (pre-MLP)
__device__ float g_Woc [Dd * Dd];        // Wo@Wc
__device__ float g_Wlk2[Dd * Dd];        // Wlk@Wo^T
__device__ float g_WoT [Dd * Dd];        // Wo^T
__device__ float g_pc  [Dd];             // W_placeholder @ Ws
__device__ int   g_mlp;                  // 1 if (W2,b2) nonzero -> general path

// ---------------- k0: transpose Wo, detect MLP-nonzero ---------------------
__global__ void k0_prep(const float* __restrict__ Wo,
                        const float* __restrict__ W2,
                        const float* __restrict__ b2)
{
    if (blockIdx.x == 0) {
        for (int i = threadIdx.x; i < Dd * Dd; i += blockDim.x) {
            int k = i >> 8, d = i & 255;
            g_WoT[d * Dd + k] = Wo[k * Dd + d];
        }
    } else {
        __shared__ int any;
        if (threadIdx.x == 0) any = 0;
        __syncthreads();
        int loc = 0;
        for (int i = threadIdx.x; i < Dd * Dd; i += blockDim.x)
            loc |= (W2[i] != 0.0f);
        if (threadIdx.x < Dd) loc |= (b2[threadIdx.x] != 0.0f);
        if (loc) atomicOr(&any, 1);
        __syncthreads();
        if (threadIdx.x == 0) g_mlp = any;
    }
}

// ---------------- k1: Woc = Wo@Wc ; Wlk2 = Wlk@Wo^T ; pc = placeholder@Ws --
__global__ void k1_weights(const float* __restrict__ Wo,
                           const float* __restrict__ Wc,
                           const float* __restrict__ Wlk,
                           const float* __restrict__ Ws,
                           const float* __restrict__ Wph)
{
    int bid = blockIdx.x;
    int d = threadIdx.x;
    if (bid < 256) {               // Woc row bid
        float acc = 0.f;
        #pragma unroll 8
        for (int j = 0; j < Dd; j++) acc += Wo[bid * Dd + j] * Wc[j * Dd + d];
        g_Woc[bid * Dd + d] = acc;
    } else if (bid < 512) {        // Wlk2 row m
        int m = bid - 256;
        float acc = 0.f;
        #pragma unroll 8
        for (int j = 0; j < Dd; j++) acc += Wlk[m * Dd + j] * g_WoT[j * Dd + d];
        g_Wlk2[m * Dd + d] = acc;
    } else {                       // pc
        float acc = 0.f;
        #pragma unroll 8
        for (int k = 0; k < 2 * Dd; k++) acc += Wph[k] * Ws[k * Dd + d];
        g_pc[d] = acc;
    }
}

// ---------------- k2: q0 = mean_n(E) @ Wc + pc ------------------------------
__global__ void k2_q0(const float* __restrict__ E, const float* __restrict__ Wc)
{
    int b = blockIdx.x, d = threadIdx.x;
    __shared__ float g[Dd];
    float s = 0.f;
    const float* Eb = E + (size_t)b * Nn * Dd + d;
    #pragma unroll 8
    for (int n = 0; n < Nn; n++) s += Eb[n * Dd];
    g[d] = s * (1.0f / Nn);
    __syncthreads();
    float acc = g_pc[d];
    #pragma unroll 8
    for (int k = 0; k < Dd; k++) acc += g[k] * Wc[k * Dd + d];
    g_q0[b * Dd + d] = acc;
}

// ---------------- k3: big GEMMs E@{Wk,Wv,Wlk2,Ws_bot} -----------------------
// grid: (colTiles=4, rowTiles=2048, w=4); block 256; 64x64 tile, TK=16
// A tile stored k-major in smem so the 4 a-values come from one LDS.128.
__global__ void __launch_bounds__(256) k3_gemm(const float* __restrict__ E,
                                               const float* __restrict__ Wk,
                                               const float* __restrict__ Wv,
                                               const float* __restrict__ Ws)
{
    const int w = blockIdx.z;
    const float* W;
    float* out;
    int transposed;
    if      (w == 0) { W = Wk;           out = g_KT;   transposed = 1; }
    else if (w == 1) { W = Wv;           out = g_V;    transposed = 0; }
    else if (w == 2) { W = g_Wlk2;       out = g_LK2T; transposed = 1; }
    else             { W = Ws + Dd * Dd; out = g_P;    transposed = 0; }

    const int rowbase = blockIdx.y * 64;
    const int colbase = blockIdx.x * 64;

    __shared__ float  Esk[16][68];      // [k][r], row pitch 68 (16B-aligned rows)
    __shared__ float4 Wsm[16][16];
    __shared__ float  Tr[64][65];

    const int tid = threadIdx.x;
    const int tx = tid & 15, ty = tid >> 4;

    float acc[4][4] = {};

    for (int kc = 0; kc < Dd; kc += 16) {
        #pragma unroll
        for (int i = 0; i < 4; i++) {
            int idx = tid + i * 256;
            int r = idx >> 4, k = idx & 15;
            Esk[k][r] = E[(size_t)(rowbase + r) * Dd + kc + k];
        }
        #pragma unroll
        for (int i = 0; i < 4; i++) {
            int idx = tid + i * 256;
            int k = idx >> 6, c = idx & 63;
            ((float*)Wsm)[k * 64 + c] = W[(kc + k) * Dd + colbase + c];
        }
        __syncthreads();
        #pragma unroll
        for (int k = 0; k < 16; k++) {
            float4 av = *(const float4*)&Esk[k][ty * 4];
            float4 bv = Wsm[k][tx];
            acc[0][0] += av.x * bv.x; acc[0][1] += av.x * bv.y; acc[0][2] += av.x * bv.z; acc[0][3] += av.x * bv.w;
            acc[1][0] += av.y * bv.x; acc[1][1] += av.y * bv.y; acc[1][2] += av.y * bv.z; acc[1][3] += av.y * bv.w;
            acc[2][0] += av.z * bv.x; acc[2][1] += av.z * bv.y; acc[2][2] += av.z * bv.z; acc[2][3] += av.z * bv.w;
            acc[3][0] += av.w * bv.x; acc[3][1] += av.w * bv.y; acc[3][2] += av.w * bv.z; acc[3][3] += av.w * bv.w;
        }
        __syncthreads();
    }

    if (!transposed) {
        #pragma unroll
        for (int i = 0; i < 4; i++) {
            float4 v = make_float4(acc[i][0], acc[i][1], acc[i][2], acc[i][3]);
            *(float4*)(out + (size_t)(rowbase + ty * 4 + i) * Dd + colbase + tx * 4) = v;
        }
    } else {
        #pragma unroll
        for (int i = 0; i < 4; i++)
            #pragma unroll
            for (int j = 0; j < 4; j++)
                Tr[ty * 4 + i][tx * 4 + j] = acc[i][j];
        __syncthreads();
        int b = rowbase >> 7;           // 64-row tiles aligned inside 128-row batch
        int nbase = rowbase & 127;
        #pragma unroll
        for (int i = 0; i < 16; i++) {
            int idx = tid + i * 256;    // 4096 elems
            int c = idx >> 6, nl = idx & 63;
            out[((size_t)b * Dd + colbase + c) * Nn + nbase + nl] = Tr[nl][c];
        }
        __syncthreads();
    }
}

// ---------------- k4: persistent per-b 128-step decode ----------------------
__global__ void __launch_bounds__(256) k4_decode(const float* __restrict__ E,
                                                 const float* __restrict__ coords,
                                                 const float* __restrict__ Ws,
                                                 const float* __restrict__ W1,
                                                 const float* __restrict__ b1,
                                                 const float* __restrict__ W2,
                                                 const float* __restrict__ b2,
                                                 float* __restrict__ out)
{
    const int b = blockIdx.x;
    const int tid = threadIdx.x;
    const int n = tid & 127, half = tid >> 7;
    const int warp = tid >> 5, lane = tid & 31;

    __shared__ float q[Dd];          // holds q * INV_SQRT_DH during compat
    __shared__ float heads[Dd];
    __shared__ float h1s[Dd];
    __shared__ float c[Nn][9];
    __shared__ float p[Hh][Nn];
    __shared__ float lp[Nn][2];
    __shared__ float ls[Nn];
    __shared__ unsigned vis[4];
    __shared__ int s_sel;
    __shared__ float s_sum[Hh];

    const int mlp = g_mlp;

    if (tid < 4) vis[tid] = 0u;
    {
        float q0 = g_q0[b * Dd + tid];
        q[tid] = mlp ? q0 : q0 * INV_SQRT_DH;   // pre-scale when MLP is identity
    }
    __syncthreads();

    if (mlp) {  // general path for residual MLP on q0
        float a1 = b1[tid];
        #pragma unroll 8
        for (int k = 0; k < Dd; k++) a1 += q[k] * W1[k * Dd + tid];
        h1s[tid] = fmaxf(a1, 0.0f);
        __syncthreads();
        float a2 = b2[tid];
        #pragma unroll 8
        for (int k = 0; k < Dd; k++) a2 += h1s[k] * W2[k * Dd + tid];
        __syncthreads();
        q[tid] = (q[tid] + a2) * INV_SQRT_DH;
        __syncthreads();
    }

    const float* KTb = g_KT   + (size_t)b * Dd * Nn;
    const float* Vb  = g_V    + (size_t)b * Nn * Dd;
    const float* LKb = g_LK2T + (size_t)b * Dd * Nn;
    const float* Pb  = g_P    + (size_t)b * Nn * Dd;

    float ll = 0.f, cost = 0.f;
    float fx = 0.f, fy = 0.f, px = 0.f, py = 0.f;
    float fctx = 0.f;  // per-thread: F[b,first][tid], set at t==0

    for (int t = 0; t < Nn; t++) {
        const bool visited = (vis[n >> 5] >> (n & 31)) & 1u;

        // ---- compat[n][h] = (q*inv_sqrt_dh)_h . K_h[n], masked ----
        {
            #pragma unroll
            for (int hh = 0; hh < 4; hh++) {
                float a = 0.f;
                if (!visited) {
                    const int dbase = half * 128 + hh * 32;
                    const float* Kp = KTb + (size_t)dbase * Nn + n;
                    #pragma unroll
                    for (int k = 0; k < 32; k++) a += q[dbase + k] * ldcg(Kp + k * Nn);
                }
                c[n][half * 4 + hh] = visited ? NEGV : a;
            }
        }
        __syncthreads();

        // ---- softmax per head (one warp per head), unnormalized exp in p --
        {
            const int h = warp;
            float m = NEGV;
            #pragma unroll
            for (int j = 0; j < 4; j++) m = fmaxf(m, c[lane + j * 32][h]);
            #pragma unroll
            for (int o = 16; o; o >>= 1) m = fmaxf(m, __shfl_xor_sync(0xffffffffu, m, o));
            float s = 0.f;
            #pragma unroll
            for (int j = 0; j < 4; j++) {
                float e = expf(c[lane + j * 32][h] - m);
                p[h][lane + j * 32] = e;
                s += e;
            }
            #pragma unroll
            for (int o = 16; o; o >>= 1) s += __shfl_xor_sync(0xffffffffu, s, o);
            if (lane == 0) s_sum[h] = s;
        }
        __syncthreads();

        // ---- heads[d] = (sum_n p * V[n,d]) / sum ----
        {
            const int d = tid, h = d >> 5;
            float acc = 0.f;
            const float* Vp = Vb + d;
            #pragma unroll 4
            for (int nn = 0; nn < Nn; nn++) {
                float pv = p[h][nn];
                if (pv != 0.0f) acc += pv * ldcg(Vp + nn * Dd);
            }
            heads[d] = acc / s_sum[h];
        }
        __syncthreads();

        // ---- logits[n] = clip*tanh( heads . LK2[b,n] / sqrt(D) ), masked --
        {
            float a = 0.f;
            if (!visited) {
                const int dbase = half * 128;
                const float* Lp = LKb + (size_t)dbase * Nn + n;
                #pragma unroll 8
                for (int k = 0; k < 128; k++) a += heads[dbase + k] * ldcg(Lp + k * Nn);
            }
            lp[n][half] = a;
        }
        __syncthreads();
        if (tid < Nn) {
            float v = visited ? NEGV
                              : CLIPV * tanhf((lp[n][0] + lp[n][1]) * INV_SQRT_D);
            ls[n] = v;
        }
        __syncthreads();

        // ---- argmax (first index on ties) + log-softmax at selected -------
        if (warp == 0) {
            float m = NEGV; int mi = Nn;
            #pragma unroll
            for (int j = 0; j < 4; j++) {
                int idx = lane + j * 32;
                float v = ls[idx];
                if (v > m || (v == m && idx < mi)) { m = v; mi = idx; }
            }
            #pragma unroll
            for (int o = 16; o; o >>= 1) {
                float vm = __shfl_xor_sync(0xffffffffu, m, o);
                int   vi = __shfl_xor_sync(0xffffffffu, mi, o);
                if (vm > m || (vm == m && vi < mi)) { m = vm; mi = vi; }
            }
            float s = 0.f;
            #pragma unroll
            for (int j = 0; j < 4; j++) s += expf(ls[lane + j * 32] - m);
            #pragma unroll
            for (int o = 16; o; o >>= 1) s += __shfl_xor_sync(0xffffffffu, s, o);
            if (lane == 0) {
                s_sel = mi;
                ll += ls[mi] - (m + logf(s));
                float cx = coords[((size_t)b * Nn + mi) * 2 + 0];
                float cy = coords[((size_t)b * Nn + mi) * 2 + 1];
                if (t == 0) { fx = cx; fy = cy; }
                else {
                    float dx = cx - px, dy = cy - py;
                    cost += sqrtf(dx * dx + dy * dy);
                }
                px = cx; py = cy;
                vis[mi >> 5] |= (1u << (mi & 31));
            }
        }
        __syncthreads();
        const int sel = s_sel;

        if (t == 0) {  // f_ctx = E[b,first] @ Ws_top  (kept in a register per thread)
            const float* Er = E + ((size_t)b * Nn + sel) * Dd;
            float a = 0.f;
            #pragma unroll 8
            for (int k = 0; k < Dd; k++) a += Er[k] * Ws[k * Dd + tid];
            fctx = a;
        }

        if (t < Nn - 1) {  // next query: heads@Woc + fctx + P[b,sel]
            float acc = fctx + ldcg(Pb + (size_t)sel * Dd + tid);
            const float* Wp = g_Woc + tid;
            #pragma unroll 8
            for (int k = 0; k < Dd; k++) acc += heads[k] * Wp[k * Dd];
            __syncthreads();
            if (mlp) {
                q[tid] = acc;
                __syncthreads();
                float a1 = b1[tid];
                #pragma unroll 8
                for (int k = 0; k < Dd; k++) a1 += q[k] * W1[k * Dd + tid];
                h1s[tid] = fmaxf(a1, 0.0f);
                __syncthreads();
                float a2 = b2[tid];
                #pragma unroll 8
                for (int k = 0; k < Dd; k++) a2 += h1s[k] * W2[k * Dd + tid];
                __syncthreads();
                q[tid] = (q[tid] + a2) * INV_SQRT_DH;
                __syncthreads();
            } else {
                q[tid] = acc * INV_SQRT_DH;   // pre-scale for next compat
                __syncthreads();
            }
        }
    }

    if (tid == 0) {
        float dx = px - fx, dy = py - fy;
        cost += sqrtf(dx * dx + dy * dy);
        out[b]      = cost;  // output tuple: (cost[B], ll[B])
        out[Bq + b] = ll;
    }
}

// ---------------- launcher ---------------------------------------------------
extern "C" void kernel_launch(void* const* d_in, const int* in_sizes, int n_in,
                              void* d_out, int out_size)
{
    const float* coords = (const float*)d_in[0];
    const float* E      = (const float*)d_in[1];
    const float* Wk     = (const float*)d_in[2];
    const float* Wv     = (const float*)d_in[3];
    const float* Wlk    = (const float*)d_in[4];
    const float* Wo     = (const float*)d_in[5];
    const float* Wc     = (const float*)d_in[6];
    const float* Ws     = (const float*)d_in[7];
    const float* Wph    = (const float*)d_in[8];
    const float* W1     = (const float*)d_in[9];
    const float* b1     = (const float*)d_in[10];
    const float* W2     = (const float*)d_in[11];
    const float* b2     = (const float*)d_in[12];
    float* out = (float*)d_out;

    // maximize L1 for k4 (Woc residency); streams bypass L1 via __ldcg
    cudaFuncSetAttribute(k4_decode, cudaFuncAttributePreferredSharedMemoryCarveout,
                         cudaSharedmemCarveoutMaxL1);

    k0_prep<<<2, 256>>>(Wo, W2, b2);
    k1_weights<<<513, 256>>>(Wo, Wc, Wlk, Ws, Wph);
    k2_q0<<<Bq, 256>>>(E, Wc);
    dim3 g3(4, 2048, 4);
    k3_gemm<<<g3, 256>>>(E, Wk, Wv, Ws);
    k4_decode<<<Bq, 256>>>(E, coords, Ws, W1, b1, W2, b2, out);
}

// round 3
// speedup vs baseline: 1.6781x; 1.6781x over previous
#include <cuda_runtime.h>
#include <cstdint>

// Problem constants
#define Bq   1024
#define Nn   128
#define Dd   256
#define Hh   8
#define DHd  32
#define NEGV (-1e9f)
#define CLIPV 10.0f
#define INV_SQRT_DH 0.17677669529663687f  // 1/sqrt(32)
#define INV_SQRT_D  0.0625f               // 1/sqrt(256)

// ---------------- scratch (device globals; no cudaMalloc allowed) ----------
__device__ float g_K   [Bq * Nn * Dd];   // [b][n][d]  (E@Wk)
__device__ float g_V   [Bq * Nn * Dd];   // [b][n][d]  (E@Wv)
__device__ float g_LK2 [Bq * Nn * Dd];   // [b][n][d]  (E@(Wlk@Wo^T))
__device__ float g_P   [Bq * Nn * Dd];   // [b][n][d]  (E@Ws_bot)
__device__ float g_q0  [Bq * Dd];        // step-0 query (pre-MLP)
__device__ float g_Woc [Dd * Dd];        // Wo@Wc
__device__ float g_Wlk2[Dd * Dd];        // Wlk@Wo^T
__device__ float g_WoT [Dd * Dd];        // Wo^T
__device__ float g_pc  [Dd];             // W_placeholder @ Ws
__device__ int   g_mlp;                  // 1 if (W2,b2) nonzero -> general path

// ---------------- k0: transpose Wo, detect MLP-nonzero ---------------------
__global__ void k0_prep(const float* __restrict__ Wo,
                        const float* __restrict__ W2,
                        const float* __restrict__ b2)
{
    if (blockIdx.x == 0) {
        for (int i = threadIdx.x; i < Dd * Dd; i += blockDim.x) {
            int k = i >> 8, d = i & 255;
            g_WoT[d * Dd + k] = Wo[k * Dd + d];
        }
    } else {
        __shared__ int any;
        if (threadIdx.x == 0) any = 0;
        __syncthreads();
        int loc = 0;
        for (int i = threadIdx.x; i < Dd * Dd; i += blockDim.x)
            loc |= (W2[i] != 0.0f);
        if (threadIdx.x < Dd) loc |= (b2[threadIdx.x] != 0.0f);
        if (loc) atomicOr(&any, 1);
        __syncthreads();
        if (threadIdx.x == 0) g_mlp = any;
    }
}

// ---------------- k1: Woc = Wo@Wc ; Wlk2 = Wlk@Wo^T ; pc = placeholder@Ws --
__global__ void k1_weights(const float* __restrict__ Wo,
                           const float* __restrict__ Wc,
                           const float* __restrict__ Wlk,
                           const float* __restrict__ Ws,
                           const float* __restrict__ Wph)
{
    int bid = blockIdx.x;
    int d = threadIdx.x;
    if (bid < 256) {               // Woc row bid
        float acc = 0.f;
        #pragma unroll 8
        for (int j = 0; j < Dd; j++) acc += Wo[bid * Dd + j] * Wc[j * Dd + d];
        g_Woc[bid * Dd + d] = acc;
    } else if (bid < 512) {        // Wlk2 row m
        int m = bid - 256;
        float acc = 0.f;
        #pragma unroll 8
        for (int j = 0; j < Dd; j++) acc += Wlk[m * Dd + j] * g_WoT[j * Dd + d];
        g_Wlk2[m * Dd + d] = acc;
    } else {                       // pc
        float acc = 0.f;
        #pragma unroll 8
        for (int k = 0; k < 2 * Dd; k++) acc += Wph[k] * Ws[k * Dd + d];
        g_pc[d] = acc;
    }
}

// ---------------- k2: q0 = mean_n(E) @ Wc + pc ------------------------------
__global__ void k2_q0(const float* __restrict__ E, const float* __restrict__ Wc)
{
    int b = blockIdx.x, d = threadIdx.x;
    __shared__ float g[Dd];
    float s = 0.f;
    const float* Eb = E + (size_t)b * Nn * Dd + d;
    #pragma unroll 8
    for (int n = 0; n < Nn; n++) s += Eb[n * Dd];
    g[d] = s * (1.0f / Nn);
    __syncthreads();
    float acc = g_pc[d];
    #pragma unroll 8
    for (int k = 0; k < Dd; k++) acc += g[k] * Wc[k * Dd + d];
    g_q0[b * Dd + d] = acc;
}

// ---------------- k3: big GEMMs E@{Wk,Wv,Wlk2,Ws_bot} -----------------------
// grid: (colTiles=4, rowTiles=2048, w=4); block 256; 64x64 tile, TK=16
// All outputs natural row-major [row][col] -> no transpose path.
__global__ void __launch_bounds__(256) k3_gemm(const float* __restrict__ E,
                                               const float* __restrict__ Wk,
                                               const float* __restrict__ Wv,
                                               const float* __restrict__ Ws)
{
    const int w = blockIdx.z;
    const float* W;
    float* out;
    if      (w == 0) { W = Wk;           out = g_K;   }
    else if (w == 1) { W = Wv;           out = g_V;   }
    else if (w == 2) { W = g_Wlk2;       out = g_LK2; }
    else             { W = Ws + Dd * Dd; out = g_P;   }

    const int rowbase = blockIdx.y * 64;
    const int colbase = blockIdx.x * 64;

    __shared__ float  Esk[16][68];      // [k][r] (A tile, k-major)
    __shared__ float4 Wsm[16][16];

    const int tid = threadIdx.x;
    const int tx = tid & 15, ty = tid >> 4;

    float acc[4][4] = {};

    for (int kc = 0; kc < Dd; kc += 16) {
        #pragma unroll
        for (int i = 0; i < 4; i++) {
            int idx = tid + i * 256;
            int r = idx >> 4, k = idx & 15;
            Esk[k][r] = E[(size_t)(rowbase + r) * Dd + kc + k];
        }
        #pragma unroll
        for (int i = 0; i < 4; i++) {
            int idx = tid + i * 256;
            int k = idx >> 6, c = idx & 63;
            ((float*)Wsm)[k * 64 + c] = W[(kc + k) * Dd + colbase + c];
        }
        __syncthreads();
        #pragma unroll
        for (int k = 0; k < 16; k++) {
            float4 av = *(const float4*)&Esk[k][ty * 4];
            float4 bv = Wsm[k][tx];
            acc[0][0] += av.x * bv.x; acc[0][1] += av.x * bv.y; acc[0][2] += av.x * bv.z; acc[0][3] += av.x * bv.w;
            acc[1][0] += av.y * bv.x; acc[1][1] += av.y * bv.y; acc[1][2] += av.y * bv.z; acc[1][3] += av.y * bv.w;
            acc[2][0] += av.z * bv.x; acc[2][1] += av.z * bv.y; acc[2][2] += av.z * bv.z; acc[2][3] += av.z * bv.w;
            acc[3][0] += av.w * bv.x; acc[3][1] += av.w * bv.y; acc[3][2] += av.w * bv.z; acc[3][3] += av.w * bv.w;
        }
        __syncthreads();
    }

    #pragma unroll
    for (int i = 0; i < 4; i++) {
        float4 v = make_float4(acc[i][0], acc[i][1], acc[i][2], acc[i][3]);
        *(float4*)(out + (size_t)(rowbase + ty * 4 + i) * Dd + colbase + tx * 4) = v;
    }
}

// ---------------- k4: persistent per-b 128-step decode ----------------------
// Warp-per-node row dots over a compact unvisited list. All global accesses
// are dense contiguous rows (LDG.128 x2 per lane), loop iterations independent.
__global__ void __launch_bounds__(256) k4_decode(const float* __restrict__ E,
                                                 const float* __restrict__ coords,
                                                 const float* __restrict__ Ws,
                                                 const float* __restrict__ W1,
                                                 const float* __restrict__ b1,
                                                 const float* __restrict__ W2,
                                                 const float* __restrict__ b2,
                                                 float* __restrict__ out)
{
    const int b = blockIdx.x;
    const int tid = threadIdx.x;
    const int warp = tid >> 5, lane = tid & 31;

    __shared__ __align__(16) float q[Dd];       // holds q * INV_SQRT_DH for compat
    __shared__ __align__(16) float heads[Dd];
    __shared__ __align__(16) float h1s[Dd];
    __shared__ float cc[Nn][9];                 // compat, compacted [j][h]
    __shared__ float pp[Hh][Nn + 4];            // exp(compat), compacted [h][j]
    __shared__ float ls_c[Nn];                  // logits, compacted [j]
    __shared__ int   list[Nn];
    __shared__ int   s_cnt, s_sel;
    __shared__ float s_sum[Hh];

    const int mlp = g_mlp;

    if (tid < Nn) list[tid] = tid;
    if (tid == 0) s_cnt = Nn;
    {
        float q0 = g_q0[b * Dd + tid];
        q[tid] = mlp ? q0 : q0 * INV_SQRT_DH;
    }
    __syncthreads();

    if (mlp) {  // general path for residual MLP on q0
        float a1 = b1[tid];
        #pragma unroll 8
        for (int k = 0; k < Dd; k++) a1 += q[k] * W1[k * Dd + tid];
        h1s[tid] = fmaxf(a1, 0.0f);
        __syncthreads();
        float a2 = b2[tid];
        #pragma unroll 8
        for (int k = 0; k < Dd; k++) a2 += h1s[k] * W2[k * Dd + tid];
        __syncthreads();
        q[tid] = (q[tid] + a2) * INV_SQRT_DH;
        __syncthreads();
    }

    const float* Kb  = g_K   + (size_t)b * Nn * Dd;
    const float* Vb  = g_V   + (size_t)b * Nn * Dd;
    const float* LKb = g_LK2 + (size_t)b * Nn * Dd;
    const float* Pb  = g_P   + (size_t)b * Nn * Dd;

    float ll = 0.f, cost = 0.f;
    float fx = 0.f, fy = 0.f, px = 0.f, py = 0.f;
    float fctx = 0.f;

    for (int t = 0; t < Nn; t++) {
        const int cnt = s_cnt;

        // ---- compat[j][h] = q_h . K_h[list[j]]  (q pre-scaled) ------------
        {
            const float4* q4 = (const float4*)q;
            float4 qa = q4[lane], qb = q4[lane + 32];
            for (int j = warp; j < cnt; j += 8) {
                const float4* Kr = (const float4*)(Kb + (size_t)list[j] * Dd);
                float4 k0 = Kr[lane], k1 = Kr[lane + 32];
                float alo = k0.x * qa.x + k0.y * qa.y + k0.z * qa.z + k0.w * qa.w;
                float ahi = k1.x * qb.x + k1.y * qb.y + k1.z * qb.z + k1.w * qb.w;
                // sum within 8-lane groups (one head each)
                #pragma unroll
                for (int o = 1; o < 8; o <<= 1) {
                    alo += __shfl_xor_sync(0xffffffffu, alo, o);
                    ahi += __shfl_xor_sync(0xffffffffu, ahi, o);
                }
                if ((lane & 7) == 0) {
                    int hg = lane >> 3;
                    cc[j][hg]     = alo;   // heads 0..3
                    cc[j][4 + hg] = ahi;   // heads 4..7
                }
            }
        }
        __syncthreads();

        // ---- softmax per head (warp h), compacted exp into pp[h][j] -------
        {
            const int h = warp;
            float m = NEGV;
            for (int j = lane; j < cnt; j += 32) m = fmaxf(m, cc[j][h]);
            #pragma unroll
            for (int o = 16; o; o >>= 1) m = fmaxf(m, __shfl_xor_sync(0xffffffffu, m, o));
            float s = 0.f;
            for (int j = lane; j < cnt; j += 32) {
                float e = expf(cc[j][h] - m);
                pp[h][j] = e;
                s += e;
            }
            #pragma unroll
            for (int o = 16; o; o >>= 1) s += __shfl_xor_sync(0xffffffffu, s, o);
            if (lane == 0) s_sum[h] = s;
        }
        __syncthreads();

        // ---- heads[d] = (sum_j pp[h][j] * V[list[j]][d]) / sum ------------
        {
            const int d = tid, h = warp;   // h == d>>5
            const float* Vp = Vb + d;
            float a0 = 0.f, a1 = 0.f;
            int j = 0;
            #pragma unroll 4
            for (; j + 2 <= cnt; j += 2) {
                a0 += pp[h][j]     * Vp[(size_t)list[j]     * Dd];
                a1 += pp[h][j + 1] * Vp[(size_t)list[j + 1] * Dd];
            }
            if (j < cnt) a0 += pp[h][j] * Vp[(size_t)list[j] * Dd];
            heads[d] = (a0 + a1) / s_sum[h];
        }
        __syncthreads();

        // ---- logits (compacted): clip*tanh( heads . LK2[list[j]] /sqrtD ) -
        {
            const float4* h4 = (const float4*)heads;
            float4 ha = h4[lane], hb = h4[lane + 32];
            for (int j = warp; j < cnt; j += 8) {
                const float4* Lr = (const float4*)(LKb + (size_t)list[j] * Dd);
                float4 l0 = Lr[lane], l1 = Lr[lane + 32];
                float a = l0.x * ha.x + l0.y * ha.y + l0.z * ha.z + l0.w * ha.w
                        + l1.x * hb.x + l1.y * hb.y + l1.z * hb.z + l1.w * hb.w;
                #pragma unroll
                for (int o = 16; o; o >>= 1) a += __shfl_xor_sync(0xffffffffu, a, o);
                if (lane == 0) ls_c[j] = CLIPV * tanhf(a * INV_SQRT_D);
            }
        }
        __syncthreads();

        // ---- argmax over compacted logits + log-softmax at selected -------
        if (warp == 0) {
            float m = NEGV; int mj = 0;
            for (int j = lane; j < cnt; j += 32) {
                float v = ls_c[j];
                if (v > m) { m = v; mj = j; }
            }
            #pragma unroll
            for (int o = 16; o; o >>= 1) {
                float vm = __shfl_xor_sync(0xffffffffu, m, o);
                int   vj = __shfl_xor_sync(0xffffffffu, mj, o);
                if (vm > m || (vm == m && vj < mj)) { m = vm; mj = vj; }
            }
            float s = 0.f;
            for (int j = lane; j < cnt; j += 32) s += expf(ls_c[j] - m);
            #pragma unroll
            for (int o = 16; o; o >>= 1) s += __shfl_xor_sync(0xffffffffu, s, o);
            if (lane == 0) {
                int n = list[mj];
                s_sel = n;
                ll += ls_c[mj] - (m + logf(s));
                float cx = coords[((size_t)b * Nn + n) * 2 + 0];
                float cy = coords[((size_t)b * Nn + n) * 2 + 1];
                if (t == 0) { fx = cx; fy = cy; }
                else {
                    float dx = cx - px, dy = cy - py;
                    cost += sqrtf(dx * dx + dy * dy);
                }
                px = cx; py = cy;
                // swap-remove from unvisited list
                list[mj] = list[cnt - 1];
                s_cnt = cnt - 1;
            }
        }
        __syncthreads();
        const int sel = s_sel;

        if (t == 0) {  // f_ctx = E[b,first] @ Ws_top (register-resident)
            const float* Er = E + ((size_t)b * Nn + sel) * Dd;
            float a = 0.f;
            #pragma unroll 8
            for (int k = 0; k < Dd; k++) a += Er[k] * Ws[k * Dd + tid];
            fctx = a;
        }

        if (t < Nn - 1) {  // next query: heads@Woc + fctx + P[b,sel]
            float base = fctx + Pb[(size_t)sel * Dd + tid];
            const float* Wp = g_Woc + tid;
            float a0 = 0.f, a1 = 0.f, a2 = 0.f, a3 = 0.f;
            #pragma unroll 8
            for (int k = 0; k < Dd; k += 4) {
                a0 += heads[k]     * Wp[(size_t)k * Dd];
                a1 += heads[k + 1] * Wp[(size_t)(k + 1) * Dd];
                a2 += heads[k + 2] * Wp[(size_t)(k + 2) * Dd];
                a3 += heads[k + 3] * Wp[(size_t)(k + 3) * Dd];
            }
            float acc = base + ((a0 + a1) + (a2 + a3));
            __syncthreads();
            if (mlp) {
                q[tid] = acc;
                __syncthreads();
                float m1 = b1[tid];
                #pragma unroll 8
                for (int k = 0; k < Dd; k++) m1 += q[k] * W1[k * Dd + tid];
                h1s[tid] = fmaxf(m1, 0.0f);
                __syncthreads();
                float m2 = b2[tid];
                #pragma unroll 8
                for (int k = 0; k < Dd; k++) m2 += h1s[k] * W2[k * Dd + tid];
                __syncthreads();
                q[tid] = (q[tid] + m2) * INV_SQRT_DH;
            } else {
                q[tid] = acc * INV_SQRT_DH;
            }
            __syncthreads();
        }
    }

    if (tid == 0) {
        float dx = px - fx, dy = py - fy;
        cost += sqrtf(dx * dx + dy * dy);
        out[b]      = cost;  // output tuple: (cost[B], ll[B])
        out[Bq + b] = ll;
    }
}

// ---------------- launcher ---------------------------------------------------
extern "C" void kernel_launch(void* const* d_in, const int* in_sizes, int n_in,
                              void* d_out, int out_size)
{
    const float* coords = (const float*)d_in[0];
    const float* E      = (const float*)d_in[1];
    const float* Wk     = (const float*)d_in[2];
    const float* Wv     = (const float*)d_in[3];
    const float* Wlk    = (const float*)d_in[4];
    const float* Wo     = (const float*)d_in[5];
    const float* Wc     = (const float*)d_in[6];
    const float* Ws     = (const float*)d_in[7];
    const float* Wph    = (const float*)d_in[8];
    const float* W1     = (const float*)d_in[9];
    const float* b1     = (const float*)d_in[10];
    const float* W2     = (const float*)d_in[11];
    const float* b2     = (const float*)d_in[12];
    float* out = (float*)d_out;

    k0_prep<<<2, 256>>>(Wo, W2, b2);
    k1_weights<<<513, 256>>>(Wo, Wc, Wlk, Ws, Wph);
    k2_q0<<<Bq, 256>>>(E, Wc);
    dim3 g3(4, 2048, 4);
    k3_gemm<<<g3, 256>>>(E, Wk, Wv, Ws);
    k4_decode<<<Bq, 256>>>(E, coords, Ws, W1, b1, W2, b2, out);
}